// round 5
// baseline (speedup 1.0000x reference)
#include <cuda_runtime.h>
#include <math.h>
#include <stdint.h>

// ---------------- problem constants ----------------
#define B_WIN   4096
#define NTOK    64
#define CDIM    512
#define NHEAD   16
#define HDIM    32
#define MTOT    (B_WIN * NTOK)      // 262144 rows
#define QKV_N   1536
#define NUM_WIN 256

// ---------------- scratch (static device globals; no allocation) ----------------
__device__ float g_qkv[402653184];            // [MTOT, 1536]
__device__ float g_attn[134217728];           // [MTOT, 512]  (tf32-rounded attn out)
__device__ float g_xcvt[134217728];           // [MTOT, 512]  (tf32-rounded x)
__device__ float g_wqkv[QKV_N * CDIM];        // tf32-rounded qkv_w
__device__ float g_wproj[CDIM * CDIM];        // tf32-rounded proj_w
__device__ float g_bias[NHEAD * NTOK * NTOK]; // [16,64,64]
__device__ float g_qkvbias[QKV_N];

// ---------------- helpers ----------------
__device__ __forceinline__ uint32_t f2tf32(float f) {
    uint32_t u;
    asm("cvt.rna.tf32.f32 %0, %1;" : "=r"(u) : "f"(f));
    return u;
}

__device__ __forceinline__ void mma_tf32(float* c, const uint32_t* a, const uint32_t* b) {
    asm volatile(
        "mma.sync.aligned.m16n8k8.row.col.f32.tf32.tf32.f32 "
        "{%0,%1,%2,%3}, {%4,%5,%6,%7}, {%8,%9}, {%0,%1,%2,%3};"
        : "+f"(c[0]), "+f"(c[1]), "+f"(c[2]), "+f"(c[3])
        : "r"(a[0]), "r"(a[1]), "r"(a[2]), "r"(a[3]), "r"(b[0]), "r"(b[1]));
}

__device__ __forceinline__ void cp16(void* smem, const void* g) {
    uint32_t s = (uint32_t)__cvta_generic_to_shared(smem);
    asm volatile("cp.async.cg.shared.global [%0], [%1], 16;" :: "r"(s), "l"(g));
}

// ---------------- tiny setup kernels ----------------
__global__ void qkvbias_kernel(const float* __restrict__ q_bias,
                               const float* __restrict__ v_bias,
                               float* __restrict__ out) {
    int i = blockIdx.x * blockDim.x + threadIdx.x;
    if (i >= QKV_N) return;
    float v;
    if (i < 512)       v = q_bias[i];
    else if (i < 1024) v = 0.0f;
    else               v = v_bias[i - 1024];
    out[i] = v;
}

// round f32 -> tf32(RNA), store f32 bits (low 13 mantissa bits zero)
__global__ void cvt_tf32_kernel(const float* __restrict__ in,
                                float* __restrict__ out, int n4) {
    int i = blockIdx.x * blockDim.x + threadIdx.x;
    if (i >= n4) return;
    float4 v = ((const float4*)in)[i];
    float4 o;
    o.x = __uint_as_float(f2tf32(v.x));
    o.y = __uint_as_float(f2tf32(v.y));
    o.z = __uint_as_float(f2tf32(v.z));
    o.w = __uint_as_float(f2tf32(v.w));
    ((float4*)out)[i] = o;
}

__device__ __forceinline__ float cpb_coord(int x) {
    float t = (float)x * (8.0f / 7.0f);
    float m = log2f(fabsf(t) + 1.0f) * (1.0f / 3.0f);
    return (t > 0.0f) ? m : ((t < 0.0f) ? -m : 0.0f);
}

__global__ void cpb_bias_kernel(const float* __restrict__ w1,
                                const float* __restrict__ b1,
                                const float* __restrict__ w2,
                                float* __restrict__ bias_out) {
    __shared__ float tableh[225];
    int h = blockIdx.x;
    int tid = threadIdx.x;
    for (int tt = tid; tt < 225; tt += blockDim.x) {
        int ih = tt / 15, iw = tt % 15;
        float t0 = cpb_coord(ih - 7);
        float t1 = cpb_coord(iw - 7);
        float val = 0.0f;
        for (int j = 0; j < 512; j++) {
            float hj = w1[2 * j] * t0 + w1[2 * j + 1] * t1 + b1[j];
            hj = fmaxf(hj, 0.0f);
            val += hj * w2[h * 512 + j];
        }
        tableh[tt] = 16.0f / (1.0f + expf(-val));
    }
    __syncthreads();
    for (int e = tid; e < NTOK * NTOK; e += blockDim.x) {
        int i = e >> 6, j = e & 63;
        int dh = (i >> 3) - (j >> 3) + 7;
        int dw = (i & 7) - (j & 7) + 7;
        bias_out[h * 4096 + e] = tableh[dh * 15 + dw];
    }
}

// ---------------- tf32 mma.sync GEMM, 128x256 tile, 64x64 warp tiles ----------------
// C[M,N] = A[M,K] @ B[N,K]^T + bias[N]
// Inputs must be pre-rounded to tf32 (RNA) in gmem; no cvt in the hot loop.
// 256 threads (8 warps, 2x4), BK=16, double-buffered cp.async.

#define BM 128
#define BN 256
#define BK 16
#define SPAD 20                      // floats per smem row (bank-conflict-free)
#define ASZ (BM * SPAD)              // 2560 floats
#define BSZ (BN * SPAD)              // 5120 floats
#define STAGE (ASZ + BSZ)            // 7680 floats
#define GEMM_SMEM_BYTES (2 * STAGE * 4)  // 61440

__global__ __launch_bounds__(256)
void mma_gemm_bias(const float* __restrict__ A,
                   const float* __restrict__ B,
                   const float* __restrict__ bias,
                   float* __restrict__ C,
                   int M, int N, int K)
{
    extern __shared__ float sm[];

    const int tid  = threadIdx.x;
    const int wid  = tid >> 5;
    const int lane = tid & 31;
    const int g    = lane >> 2;   // 0..7
    const int t    = lane & 3;    // 0..3

    const int wm = (wid >> 2) * 64;   // 0 or 64
    const int wn = (wid & 3) * 64;    // 0,64,128,192

    const int bm = blockIdx.y * BM;
    const int bn = blockIdx.x * BN;

    const int lrow = tid >> 2;        // 0..63
    const int lc4  = (tid & 3) * 4;   // 0,4,8,12

    const float* Abase = A + (size_t)bm * K;
    const float* Bbase = B + (size_t)bn * K;

    float acc[4][8][4];
#pragma unroll
    for (int i = 0; i < 4; i++)
#pragma unroll
        for (int j = 0; j < 8; j++)
#pragma unroll
            for (int r = 0; r < 4; r++) acc[i][j][r] = 0.0f;

    const int NIT = K / BK;

    auto issue = [&](int s, int k0) {
        float* As = sm + s * STAGE;
        float* Bs = sm + s * STAGE + ASZ;
        // A: 128 rows, 2 rows per thread
        cp16(&As[lrow * SPAD + lc4],        &Abase[(size_t)lrow * K + k0 + lc4]);
        cp16(&As[(lrow + 64) * SPAD + lc4], &Abase[(size_t)(lrow + 64) * K + k0 + lc4]);
        // B: 256 rows, 4 rows per thread
#pragma unroll
        for (int p = 0; p < 4; p++) {
            int row = lrow + p * 64;
            cp16(&Bs[row * SPAD + lc4], &Bbase[(size_t)row * K + k0 + lc4]);
        }
    };

    issue(0, 0);
    asm volatile("cp.async.commit_group;");

    for (int it = 0; it < NIT; it++) {
        if (it + 1 < NIT) {
            issue((it + 1) & 1, (it + 1) * BK);
            asm volatile("cp.async.commit_group;");
            asm volatile("cp.async.wait_group 1;");
        } else {
            asm volatile("cp.async.wait_group 0;");
        }
        __syncthreads();

        const float* As = sm + (it & 1) * STAGE;
        const float* Bs = sm + (it & 1) * STAGE + ASZ;

#pragma unroll
        for (int ks = 0; ks < BK; ks += 8) {
            uint32_t af[4][4];
#pragma unroll
            for (int mf = 0; mf < 4; mf++) {
                const float* base = As + (wm + mf * 16) * SPAD + ks;
                af[mf][0] = __float_as_uint(base[g * SPAD + t]);
                af[mf][1] = __float_as_uint(base[(g + 8) * SPAD + t]);
                af[mf][2] = __float_as_uint(base[g * SPAD + t + 4]);
                af[mf][3] = __float_as_uint(base[(g + 8) * SPAD + t + 4]);
            }
            uint32_t bf[8][2];
#pragma unroll
            for (int nf = 0; nf < 8; nf++) {
                const float* base = Bs + (wn + nf * 8) * SPAD + ks;
                bf[nf][0] = __float_as_uint(base[g * SPAD + t]);
                bf[nf][1] = __float_as_uint(base[g * SPAD + t + 4]);
            }
#pragma unroll
            for (int mf = 0; mf < 4; mf++)
#pragma unroll
                for (int nf = 0; nf < 8; nf++)
                    mma_tf32(acc[mf][nf], af[mf], bf[nf]);
        }
        __syncthreads();
    }

    // epilogue: add bias, store
#pragma unroll
    for (int mf = 0; mf < 4; mf++) {
#pragma unroll
        for (int nf = 0; nf < 8; nf++) {
            int row0 = bm + wm + mf * 16 + g;
            int col  = bn + wn + nf * 8 + 2 * t;
            float b0 = bias[col], b1 = bias[col + 1];
            float2 o0 = {acc[mf][nf][0] + b0, acc[mf][nf][1] + b1};
            float2 o1 = {acc[mf][nf][2] + b0, acc[mf][nf][3] + b1};
            *(float2*)&C[(size_t)row0 * N + col]       = o0;
            *(float2*)&C[(size_t)(row0 + 8) * N + col] = o1;
        }
    }
}

// ---------------- fused cosine attention per (window, head) ----------------
__global__ __launch_bounds__(256)
void attn_kernel(const float* __restrict__ qkv,
                 const float* __restrict__ mask,
                 const float* __restrict__ logit_scale,
                 const float* __restrict__ bias,
                 float* __restrict__ out)
{
    __shared__ float qs[NTOK][HDIM + 1];
    __shared__ float ks[NTOK][HDIM + 1];
    __shared__ float vs[NTOK][HDIM + 1];
    __shared__ float S[NTOK][NTOK + 1];

    const int w = blockIdx.x;
    const int h = blockIdx.y;
    const int tid = threadIdx.x;

    const float* base = qkv + (size_t)w * NTOK * QKV_N + h * HDIM;

    for (int idx = tid; idx < NTOK * HDIM / 4; idx += 256) {
        int n = idx >> 3;
        int d = (idx & 7) * 4;
        const float* r = base + n * QKV_N + d;
        float4 q4 = *(const float4*)(r);
        float4 k4 = *(const float4*)(r + 512);
        float4 v4 = *(const float4*)(r + 1024);
        qs[n][d] = q4.x; qs[n][d + 1] = q4.y; qs[n][d + 2] = q4.z; qs[n][d + 3] = q4.w;
        ks[n][d] = k4.x; ks[n][d + 1] = k4.y; ks[n][d + 2] = k4.z; ks[n][d + 3] = k4.w;
        vs[n][d] = v4.x; vs[n][d + 1] = v4.y; vs[n][d + 2] = v4.z; vs[n][d + 3] = v4.w;
    }
    __syncthreads();

    const float scale = expf(fminf(logit_scale[h], 4.605170186f)); // ln(100)
    if (tid < 128) {
        int r = tid & 63;
        float* row = (tid < 64) ? qs[r] : ks[r];
        float ss = 0.0f;
#pragma unroll
        for (int d = 0; d < HDIM; d++) ss += row[d] * row[d];
        float rn = rsqrtf(ss);
        if (tid < 64) rn *= scale;
#pragma unroll
        for (int d = 0; d < HDIM; d++) row[d] *= rn;
    }
    __syncthreads();

    {
        const int i = tid >> 2;
        const int jb = (tid & 3) * 16;
        const float* bh = bias + h * 4096 + i * 64;
        const float* mh = mask + (size_t)(w & (NUM_WIN - 1)) * 4096 + i * 64;
#pragma unroll
        for (int j = 0; j < 16; j++) {
            float dot = 0.0f;
#pragma unroll
            for (int d = 0; d < HDIM; d++) dot = fmaf(qs[i][d], ks[jb + j][d], dot);
            S[i][jb + j] = dot + bh[jb + j] + mh[jb + j];
        }
    }
    __syncthreads();

    if (tid < NTOK) {
        float mx = -1e30f;
#pragma unroll
        for (int j = 0; j < NTOK; j++) mx = fmaxf(mx, S[tid][j]);
        float sum = 0.0f;
#pragma unroll
        for (int j = 0; j < NTOK; j++) {
            float e = expf(S[tid][j] - mx);
            S[tid][j] = e;
            sum += e;
        }
        float inv = 1.0f / sum;
#pragma unroll
        for (int j = 0; j < NTOK; j++) S[tid][j] *= inv;
    }
    __syncthreads();

    {
        const int i = tid >> 2;
        const int db = (tid & 3) * 8;
        float o[8];
#pragma unroll
        for (int d = 0; d < 8; d++) o[d] = 0.0f;
#pragma unroll
        for (int m = 0; m < NTOK; m++) {
            float s = S[i][m];
#pragma unroll
            for (int d = 0; d < 8; d++) o[d] = fmaf(s, vs[m][db + d], o[d]);
        }
        // store tf32-rounded so the proj GEMM sees valid tf32 operands
        float* op = out + (size_t)(w * NTOK + i) * CDIM + h * HDIM + db;
        float4 o0, o1;
        o0.x = __uint_as_float(f2tf32(o[0])); o0.y = __uint_as_float(f2tf32(o[1]));
        o0.z = __uint_as_float(f2tf32(o[2])); o0.w = __uint_as_float(f2tf32(o[3]));
        o1.x = __uint_as_float(f2tf32(o[4])); o1.y = __uint_as_float(f2tf32(o[5]));
        o1.z = __uint_as_float(f2tf32(o[6])); o1.w = __uint_as_float(f2tf32(o[7]));
        *(float4*)(op)     = o0;
        *(float4*)(op + 4) = o1;
    }
}

// ---------------- launch ----------------
extern "C" void kernel_launch(void* const* d_in, const int* in_sizes, int n_in,
                              void* d_out, int out_size)
{
    const float* x           = (const float*)d_in[0];
    const float* mask        = (const float*)d_in[1];
    const float* qkv_w       = (const float*)d_in[2];
    const float* q_bias      = (const float*)d_in[3];
    const float* v_bias      = (const float*)d_in[4];
    const float* logit_scale = (const float*)d_in[5];
    const float* cpb_w1      = (const float*)d_in[6];
    const float* cpb_b1      = (const float*)d_in[7];
    const float* cpb_w2      = (const float*)d_in[8];
    const float* proj_w      = (const float*)d_in[9];
    const float* proj_b      = (const float*)d_in[10];
    float* out = (float*)d_out;

    float *qkv_buf, *attn_buf, *xcvt_buf, *wqkv_buf, *wproj_buf, *bias_buf, *qb_buf;
    cudaGetSymbolAddress((void**)&qkv_buf, g_qkv);
    cudaGetSymbolAddress((void**)&attn_buf, g_attn);
    cudaGetSymbolAddress((void**)&xcvt_buf, g_xcvt);
    cudaGetSymbolAddress((void**)&wqkv_buf, g_wqkv);
    cudaGetSymbolAddress((void**)&wproj_buf, g_wproj);
    cudaGetSymbolAddress((void**)&bias_buf, g_bias);
    cudaGetSymbolAddress((void**)&qb_buf, g_qkvbias);

    cudaFuncSetAttribute(mma_gemm_bias,
                         cudaFuncAttributeMaxDynamicSharedMemorySize, GEMM_SMEM_BYTES);

    qkvbias_kernel<<<(QKV_N + 255) / 256, 256>>>(q_bias, v_bias, qb_buf);
    cpb_bias_kernel<<<NHEAD, 256>>>(cpb_w1, cpb_b1, cpb_w2, bias_buf);

    // tf32 pre-rounding passes (operands carry valid tf32 bit patterns)
    cvt_tf32_kernel<<<(MTOT * CDIM / 4 + 255) / 256, 256>>>(x, xcvt_buf, MTOT * CDIM / 4);
    cvt_tf32_kernel<<<(QKV_N * CDIM / 4 + 255) / 256, 256>>>(qkv_w, wqkv_buf, QKV_N * CDIM / 4);
    cvt_tf32_kernel<<<(CDIM * CDIM / 4 + 255) / 256, 256>>>(proj_w, wproj_buf, CDIM * CDIM / 4);

    // QKV projection: [262144,512] @ [1536,512]^T
    {
        dim3 grid(QKV_N / BN, MTOT / BM);   // (6, 2048)
        mma_gemm_bias<<<grid, 256, GEMM_SMEM_BYTES>>>(xcvt_buf, wqkv_buf, qb_buf, qkv_buf,
                                                      MTOT, QKV_N, CDIM);
    }

    // attention
    {
        dim3 grid(B_WIN, NHEAD);
        attn_kernel<<<grid, 256>>>(qkv_buf, mask, logit_scale, bias_buf, attn_buf);
    }

    // output projection: [262144,512] @ [512,512]^T -> d_out
    {
        dim3 grid(CDIM / BN, MTOT / BM);    // (2, 2048)
        mma_gemm_bias<<<grid, 256, GEMM_SMEM_BYTES>>>(attn_buf, wproj_buf, proj_b, out,
                                                      MTOT, CDIM, CDIM);
    }
}